// round 1
// baseline (speedup 1.0000x reference)
#include <cuda_runtime.h>
#include <math.h>

// Problem constants (fixed by the reference setup_inputs)
#define NB   64
#define CC   128
#define HH   56
#define WW   56
#define EPS  1e-5f

// Intermediate activation buffer (conv1->bn1->relu output).
// Static __device__ array: allowed (no cudaMalloc).
__device__ float g_mid[NB * CC * HH * WW];

// Tiling:
//   CTA: 32 output channels x 4 output rows x 56 cols, one image.
//   Threads 256: w_g = tid&7 (7 cols each), h_g = (tid>>3)&1 (2 rows each),
//                co_g = tid>>4 (2 channels each) -> 2*2*7 = 28 accumulators.
//   K loop: ci in chunks of 16; smem holds x tile [16][6][58] and w tile [32][144].
//
// MODE 0: in = param x, out = g_mid            (conv1 + bn1 + relu)
// MODE 1: in = g_mid,   out = param, +residual (conv2 + bn2 + add + relu)
template <int MODE>
__global__ __launch_bounds__(256, 2)
void conv_bn_relu_kernel(const float* __restrict__ x_in,
                         const float* __restrict__ wgt,
                         const float* __restrict__ gamma,
                         const float* __restrict__ beta,
                         const float* __restrict__ mean,
                         const float* __restrict__ var,
                         const float* __restrict__ resid,
                         float* __restrict__ out_p)
{
    __shared__ float xs[16][6][58];   // [ci][row][col]  (rows h0-1..h0+4, cols -1..56)
    __shared__ float ws[32][144];     // [co][ci*9 + kh*3 + kw]

    const int hb  = blockIdx.x;           // 0..13
    const int cob = blockIdx.y;           // 0..3
    const int n   = blockIdx.z;           // 0..63
    const int h0  = hb * 4;
    const int co0 = cob * 32;

    const int tid  = threadIdx.x;
    const int w_g  = tid & 7;              // 0..7  -> 7 cols each
    const int h_g  = (tid >> 3) & 1;       // 0..1  -> 2 rows each
    const int co_g = tid >> 4;             // 0..15 -> 2 channels each

    const float* src = (MODE == 0) ? x_in : g_mid;

    float acc[2][2][7];
#pragma unroll
    for (int a = 0; a < 2; a++)
#pragma unroll
        for (int b = 0; b < 2; b++)
#pragma unroll
            for (int c = 0; c < 7; c++)
                acc[a][b][c] = 0.0f;

#pragma unroll 1
    for (int ci0 = 0; ci0 < CC; ci0 += 16) {
        // ---- stage x tile: 16 ci x 6 rows x 58 cols ----
#pragma unroll 1
        for (int i = tid; i < 16 * 6 * 58; i += 256) {
            int ci  = i / (6 * 58);
            int rem = i - ci * (6 * 58);
            int r   = rem / 58;
            int c   = rem - r * 58;
            int hin = h0 + r - 1;
            int win = c - 1;
            float v = 0.0f;
            if (hin >= 0 && hin < HH && win >= 0 && win < WW)
                v = src[((n * CC + ci0 + ci) * HH + hin) * WW + win];
            xs[ci][r][c] = v;
        }
        // ---- stage weights: 32 co x (16 ci * 9) contiguous per co ----
#pragma unroll 1
        for (int i = tid; i < 32 * 144; i += 256) {
            int co = i / 144;
            int k  = i - co * 144;
            ws[co][k] = wgt[(co0 + co) * (CC * 9) + ci0 * 9 + k];
        }
        __syncthreads();

        // ---- compute ----
#pragma unroll 1
        for (int ci = 0; ci < 16; ci++) {
#pragma unroll
            for (int kh = 0; kh < 3; kh++) {
                const int r0 = h_g * 2 + kh;        // smem row for hh=0
                float xr0[9], xr1[9];
#pragma unroll
                for (int j = 0; j < 9; j++) {
                    xr0[j] = xs[ci][r0][w_g * 7 + j];
                    xr1[j] = xs[ci][r0 + 1][w_g * 7 + j];
                }
#pragma unroll
                for (int kw = 0; kw < 3; kw++) {
                    const float w0 = ws[co_g * 2 + 0][ci * 9 + kh * 3 + kw];
                    const float w1 = ws[co_g * 2 + 1][ci * 9 + kh * 3 + kw];
#pragma unroll
                    for (int j = 0; j < 7; j++) {
                        acc[0][0][j] = fmaf(w0, xr0[j + kw], acc[0][0][j]);
                        acc[0][1][j] = fmaf(w0, xr1[j + kw], acc[0][1][j]);
                        acc[1][0][j] = fmaf(w1, xr0[j + kw], acc[1][0][j]);
                        acc[1][1][j] = fmaf(w1, xr1[j + kw], acc[1][1][j]);
                    }
                }
            }
        }
        __syncthreads();
    }

    // ---- epilogue: BN fold + relu (+ residual) ----
#pragma unroll
    for (int cc = 0; cc < 2; cc++) {
        const int co = co0 + co_g * 2 + cc;
        const float s = gamma[co] * rsqrtf(var[co] + EPS);
        const float b = beta[co] - mean[co] * s;
#pragma unroll
        for (int hh = 0; hh < 2; hh++) {
            const int oh = h0 + h_g * 2 + hh;
#pragma unroll
            for (int j = 0; j < 7; j++) {
                const int ow  = w_g * 7 + j;
                const long idx = ((long)(n * CC + co) * HH + oh) * WW + ow;
                float v = fmaf(acc[cc][hh][j], s, b);
                if (MODE == 1) v += resid[idx];
                v = fmaxf(v, 0.0f);
                if (MODE == 0) g_mid[idx] = v;
                else           out_p[idx] = v;
            }
        }
    }
}

extern "C" void kernel_launch(void* const* d_in, const int* in_sizes, int n_in,
                              void* d_out, int out_size)
{
    const float* x      = (const float*)d_in[0];
    const float* w1     = (const float*)d_in[1];
    const float* w2     = (const float*)d_in[2];
    const float* gamma1 = (const float*)d_in[3];
    const float* beta1  = (const float*)d_in[4];
    const float* mean1  = (const float*)d_in[5];
    const float* var1   = (const float*)d_in[6];
    const float* gamma2 = (const float*)d_in[7];
    const float* beta2  = (const float*)d_in[8];
    const float* mean2  = (const float*)d_in[9];
    const float* var2   = (const float*)d_in[10];
    float* out = (float*)d_out;

    dim3 grid(HH / 4, CC / 32, NB);   // 14 x 4 x 64
    dim3 block(256);

    // conv1 + bn1 + relu -> g_mid
    conv_bn_relu_kernel<0><<<grid, block>>>(x, w1, gamma1, beta1, mean1, var1,
                                            nullptr, nullptr);
    // conv2 + bn2 + residual(x) + relu -> out
    conv_bn_relu_kernel<1><<<grid, block>>>(nullptr, w2, gamma2, beta2, mean2, var2,
                                            x, out);
}

// round 2
// speedup vs baseline: 1.0002x; 1.0002x over previous
#include <cuda_runtime.h>
#include <math.h>

// Problem constants (fixed by the reference setup_inputs)
#define NB   64
#define CC   128
#define HH   56
#define WW   56
#define EPS  1e-5f

// Intermediate activation buffer (conv1->bn1->relu output).
// Static __device__ array: allowed (no cudaMalloc).
__device__ float g_mid[NB * CC * HH * WW];

// Tiling:
//   CTA: 32 output channels x 4 output rows x 56 cols, one image.
//   Threads 256: w_g = tid&7 (7 cols each), h_g = (tid>>3)&1 (2 rows each),
//                co_g = tid>>4 (2 channels each) -> 2*2*7 = 28 accumulators.
//   K loop: ci in chunks of 16; smem holds x tile [16][6][58] and w tile [32][144].
//
// MODE 0: in = param x, out = g_mid            (conv1 + bn1 + relu)
// MODE 1: in = g_mid,   out = param, +residual (conv2 + bn2 + add + relu)
template <int MODE>
__global__ __launch_bounds__(256, 2)
void conv_bn_relu_kernel(const float* __restrict__ x_in,
                         const float* __restrict__ wgt,
                         const float* __restrict__ gamma,
                         const float* __restrict__ beta,
                         const float* __restrict__ mean,
                         const float* __restrict__ var,
                         const float* __restrict__ resid,
                         float* __restrict__ out_p)
{
    __shared__ float xs[16][6][58];   // [ci][row][col]  (rows h0-1..h0+4, cols -1..56)
    __shared__ float ws[32][144];     // [co][ci*9 + kh*3 + kw]

    const int hb  = blockIdx.x;           // 0..13
    const int cob = blockIdx.y;           // 0..3
    const int n   = blockIdx.z;           // 0..63
    const int h0  = hb * 4;
    const int co0 = cob * 32;

    const int tid  = threadIdx.x;
    const int w_g  = tid & 7;              // 0..7  -> 7 cols each
    const int h_g  = (tid >> 3) & 1;       // 0..1  -> 2 rows each
    const int co_g = tid >> 4;             // 0..15 -> 2 channels each

    const float* src = (MODE == 0) ? x_in : g_mid;

    float acc[2][2][7];
#pragma unroll
    for (int a = 0; a < 2; a++)
#pragma unroll
        for (int b = 0; b < 2; b++)
#pragma unroll
            for (int c = 0; c < 7; c++)
                acc[a][b][c] = 0.0f;

#pragma unroll 1
    for (int ci0 = 0; ci0 < CC; ci0 += 16) {
        // ---- stage x tile: 16 ci x 6 rows x 58 cols ----
#pragma unroll 1
        for (int i = tid; i < 16 * 6 * 58; i += 256) {
            int ci  = i / (6 * 58);
            int rem = i - ci * (6 * 58);
            int r   = rem / 58;
            int c   = rem - r * 58;
            int hin = h0 + r - 1;
            int win = c - 1;
            float v = 0.0f;
            if (hin >= 0 && hin < HH && win >= 0 && win < WW)
                v = src[((n * CC + ci0 + ci) * HH + hin) * WW + win];
            xs[ci][r][c] = v;
        }
        // ---- stage weights: 32 co x (16 ci * 9) contiguous per co ----
#pragma unroll 1
        for (int i = tid; i < 32 * 144; i += 256) {
            int co = i / 144;
            int k  = i - co * 144;
            ws[co][k] = wgt[(co0 + co) * (CC * 9) + ci0 * 9 + k];
        }
        __syncthreads();

        // ---- compute ----
#pragma unroll 1
        for (int ci = 0; ci < 16; ci++) {
#pragma unroll
            for (int kh = 0; kh < 3; kh++) {
                const int r0 = h_g * 2 + kh;        // smem row for hh=0
                float xr0[9], xr1[9];
#pragma unroll
                for (int j = 0; j < 9; j++) {
                    xr0[j] = xs[ci][r0][w_g * 7 + j];
                    xr1[j] = xs[ci][r0 + 1][w_g * 7 + j];
                }
#pragma unroll
                for (int kw = 0; kw < 3; kw++) {
                    const float w0 = ws[co_g * 2 + 0][ci * 9 + kh * 3 + kw];
                    const float w1 = ws[co_g * 2 + 1][ci * 9 + kh * 3 + kw];
#pragma unroll
                    for (int j = 0; j < 7; j++) {
                        acc[0][0][j] = fmaf(w0, xr0[j + kw], acc[0][0][j]);
                        acc[0][1][j] = fmaf(w0, xr1[j + kw], acc[0][1][j]);
                        acc[1][0][j] = fmaf(w1, xr0[j + kw], acc[1][0][j]);
                        acc[1][1][j] = fmaf(w1, xr1[j + kw], acc[1][1][j]);
                    }
                }
            }
        }
        __syncthreads();
    }

    // ---- epilogue: BN fold + relu (+ residual) ----
#pragma unroll
    for (int cc = 0; cc < 2; cc++) {
        const int co = co0 + co_g * 2 + cc;
        const float s = gamma[co] * rsqrtf(var[co] + EPS);
        const float b = beta[co] - mean[co] * s;
#pragma unroll
        for (int hh = 0; hh < 2; hh++) {
            const int oh = h0 + h_g * 2 + hh;
#pragma unroll
            for (int j = 0; j < 7; j++) {
                const int ow  = w_g * 7 + j;
                const long idx = ((long)(n * CC + co) * HH + oh) * WW + ow;
                float v = fmaf(acc[cc][hh][j], s, b);
                if (MODE == 1) v += resid[idx];
                v = fmaxf(v, 0.0f);
                if (MODE == 0) g_mid[idx] = v;
                else           out_p[idx] = v;
            }
        }
    }
}

extern "C" void kernel_launch(void* const* d_in, const int* in_sizes, int n_in,
                              void* d_out, int out_size)
{
    const float* x      = (const float*)d_in[0];
    const float* w1     = (const float*)d_in[1];
    const float* w2     = (const float*)d_in[2];
    const float* gamma1 = (const float*)d_in[3];
    const float* beta1  = (const float*)d_in[4];
    const float* mean1  = (const float*)d_in[5];
    const float* var1   = (const float*)d_in[6];
    const float* gamma2 = (const float*)d_in[7];
    const float* beta2  = (const float*)d_in[8];
    const float* mean2  = (const float*)d_in[9];
    const float* var2   = (const float*)d_in[10];
    float* out = (float*)d_out;

    dim3 grid(HH / 4, CC / 32, NB);   // 14 x 4 x 64
    dim3 block(256);

    // conv1 + bn1 + relu -> g_mid
    conv_bn_relu_kernel<0><<<grid, block>>>(x, w1, gamma1, beta1, mean1, var1,
                                            nullptr, nullptr);
    // conv2 + bn2 + residual(x) + relu -> out
    conv_bn_relu_kernel<1><<<grid, block>>>(nullptr, w2, gamma2, beta2, mean2, var2,
                                            x, out);
}

// round 4
// speedup vs baseline: 3.1258x; 3.1252x over previous
#include <cuda_runtime.h>
#include <cuda_bf16.h>
#include <cstdint>
#include <math.h>

#define NB   64
#define HHH  56
#define WWW  56
#define EPS  1e-5f

// ---------------- global scratch (no cudaMalloc allowed) ----------------
#define NHWC_ELEMS (NB * HHH * WWW * 128)
__device__ __align__(16) __nv_bfloat16 g_xhi[NHWC_ELEMS];
__device__ __align__(16) __nv_bfloat16 g_xlo[NHWC_ELEMS];
__device__ __align__(16) __nv_bfloat16 g_mhi[NHWC_ELEMS];
__device__ __align__(16) __nv_bfloat16 g_mlo[NHWC_ELEMS];
#define WT_ELEMS (9 * 128 * 128)           // [tap][co][ci]
__device__ __align__(16) __nv_bfloat16 g_w1hi[WT_ELEMS];
__device__ __align__(16) __nv_bfloat16 g_w1lo[WT_ELEMS];
__device__ __align__(16) __nv_bfloat16 g_w2hi[WT_ELEMS];
__device__ __align__(16) __nv_bfloat16 g_w2lo[WT_ELEMS];

// ---------------- smem layout (bytes) ----------------
// X tile: 160 rows (16 cols x 10 rows halo) x 40 bf16 (32 used + 8 pad) = 80B/row
// W tile: 128 co x 40 bf16 = 80B/row
#define XS_HI      0
#define XS_LO      12800
#define WS_HI      25600
#define WS_LO      35840
#define SMEM_BYTES 46080        // fits default 48KB dynamic smem

__device__ __forceinline__ uint32_t smem_u32(const void* p) {
    uint32_t a;
    asm("{ .reg .u64 t; cvta.to.shared.u64 t, %1; cvt.u32.u64 %0, t; }" : "=r"(a) : "l"(p));
    return a;
}

#define LDSM_X4(r, addr)                                                       \
    asm volatile("ldmatrix.sync.aligned.m8n8.x4.shared.b16 {%0,%1,%2,%3}, [%4];" \
        : "=r"((r)[0]), "=r"((r)[1]), "=r"((r)[2]), "=r"((r)[3]) : "r"(addr))
#define LDSM_X2(r, addr)                                                       \
    asm volatile("ldmatrix.sync.aligned.m8n8.x2.shared.b16 {%0,%1}, [%2];"     \
        : "=r"((r)[0]), "=r"((r)[1]) : "r"(addr))

__device__ __forceinline__ void mma16816(float* d, const uint32_t* a, const uint32_t* b) {
    asm volatile(
        "mma.sync.aligned.m16n8k16.row.col.f32.bf16.bf16.f32 "
        "{%0,%1,%2,%3}, {%4,%5,%6,%7}, {%8,%9}, {%0,%1,%2,%3};"
        : "+f"(d[0]), "+f"(d[1]), "+f"(d[2]), "+f"(d[3])
        : "r"(a[0]), "r"(a[1]), "r"(a[2]), "r"(a[3]), "r"(b[0]), "r"(b[1]));
}

// ---- prep: NCHW fp32 x -> NHWC bf16 hi/lo ----
__global__ void prep_x(const float* __restrict__ x) {
    __shared__ float s[128][57];
    const int n = blockIdx.y, h = blockIdx.x;
    for (int i = threadIdx.x; i < 128 * 56; i += blockDim.x) {
        int ci = i / 56, w = i - ci * 56;
        s[ci][w] = x[((long)(n * 128 + ci) * 56 + h) * 56 + w];
    }
    __syncthreads();
    for (int i = threadIdx.x; i < 128 * 56; i += blockDim.x) {
        int w = i >> 7, ci = i & 127;
        float v = s[ci][w];
        __nv_bfloat16 hi = __float2bfloat16(v);
        __nv_bfloat16 lo = __float2bfloat16(v - __bfloat162float(hi));
        long idx = ((long)(n * 56 + h) * 56 + w) * 128 + ci;
        g_xhi[idx] = hi; g_xlo[idx] = lo;
    }
}

// ---- prep: OIHW fp32 w -> [tap][co][ci] bf16 hi/lo ----
__global__ void prep_w(const float* __restrict__ w1, const float* __restrict__ w2) {
    int i = blockIdx.x * blockDim.x + threadIdx.x;
    if (i >= 2 * WT_ELEMS) return;
    int conv = i / WT_ELEMS;
    int rem  = i - conv * WT_ELEMS;
    int tap  = rem >> 14;
    int co   = (rem >> 7) & 127;
    int ci   = rem & 127;
    int kh = tap / 3, kw = tap - kh * 3;
    const float* w = conv ? w2 : w1;
    float v = w[((co * 128 + ci) * 3 + kh) * 3 + kw];
    __nv_bfloat16 hi = __float2bfloat16(v);
    __nv_bfloat16 lo = __float2bfloat16(v - __bfloat162float(hi));
    if (conv) { g_w2hi[rem] = hi; g_w2lo[rem] = lo; }
    else      { g_w1hi[rem] = hi; g_w1lo[rem] = lo; }
}

// MODE 0: src g_x*, w1, BN1, relu -> g_m* (NHWC bf16 hi/lo)
// MODE 1: src g_m*, w2, BN2, +x(NCHW), relu -> out (NCHW fp32)
template <int MODE>
__global__ void __launch_bounds__(256)
conv_mma(const float* __restrict__ gamma, const float* __restrict__ beta,
         const float* __restrict__ mean,  const float* __restrict__ var,
         const float* __restrict__ resid, float* __restrict__ outp)
{
    extern __shared__ char smem[];
    const uint32_t sb = smem_u32(smem);
    const int tid  = threadIdx.x;
    const int lane = tid & 31;
    const int wid  = tid >> 5;
    const int warpM = wid & 3;        // 0..3 -> co tile of 32
    const int warpN = wid >> 2;       // 0..1 -> q tile of 56
    const int n  = blockIdx.z;
    const int h0 = blockIdx.y * 8;
    const int c0 = blockIdx.x * 14;

    const __nv_bfloat16* shi = (MODE == 0) ? g_xhi : g_mhi;
    const __nv_bfloat16* slo = (MODE == 0) ? g_xlo : g_mlo;
    const __nv_bfloat16* whi = (MODE == 0) ? g_w1hi : g_w2hi;
    const __nv_bfloat16* wlo = (MODE == 0) ? g_w1lo : g_w2lo;

    float acc[2][7][4];
#pragma unroll
    for (int t = 0; t < 2; t++)
#pragma unroll
        for (int j = 0; j < 7; j++)
#pragma unroll
            for (int e = 0; e < 4; e++)
                acc[t][j][e] = 0.0f;

    const int m0 = warpM * 32;
    const uint32_t a_off = (uint32_t)(m0 + (lane & 15)) * 80 + ((lane >> 4) & 1) * 16;
    const uint32_t b_lane_off = (uint32_t)(lane & 7) * 80 + ((lane >> 3) & 1) * 16;

    for (int chunk = 0; chunk < 4; chunk++) {
        const int ci0 = chunk * 32;
        // ---- stage X halo: 16 cols x 10 rows x 32 ci, both parts ----
#pragma unroll
        for (int p = 0; p < 2; p++) {
            const __nv_bfloat16* src = p ? slo : shi;
            const uint32_t dstb = p ? XS_LO : XS_HI;
            for (int i = tid; i < 640; i += 256) {
                int row = i >> 2, seg = i & 3;
                int cx = row / 10, rh = row - cx * 10;
                int h = h0 + rh - 1, w = c0 + cx - 1;
                uint4 v = make_uint4(0u, 0u, 0u, 0u);
                if ((unsigned)h < 56u && (unsigned)w < 56u)
                    v = *reinterpret_cast<const uint4*>(
                        src + (((long)(n * 56 + h) * 56 + w) * 128 + ci0 + seg * 8));
                *reinterpret_cast<uint4*>(smem + dstb + row * 80 + seg * 16) = v;
            }
        }
        for (int tap = 0; tap < 9; tap++) {
            const int kh = tap / 3, kw = tap - kh * 3;
            // ---- stage W for this tap: 128 co x 32 ci, both parts ----
#pragma unroll
            for (int p = 0; p < 2; p++) {
                const __nv_bfloat16* wsrc = p ? wlo : whi;
                const uint32_t dstb = p ? WS_LO : WS_HI;
                for (int i = tid; i < 512; i += 256) {
                    int co = i >> 2, seg = i & 3;
                    uint4 v = *reinterpret_cast<const uint4*>(
                        wsrc + ((long)(tap * 128 + co)) * 128 + ci0 + seg * 8);
                    *reinterpret_cast<uint4*>(smem + dstb + co * 80 + seg * 16) = v;
                }
            }
            __syncthreads();

            const uint32_t brow = (uint32_t)((warpN * 7 + kw) * 10 + kh) * 80 + b_lane_off;
#pragma unroll
            for (int k16 = 0; k16 < 2; k16++) {
                const uint32_t koff = k16 * 32;
                uint32_t ahi[2][4], alo[2][4];
                LDSM_X4(ahi[0], sb + WS_HI + a_off + koff);
                LDSM_X4(ahi[1], sb + WS_HI + a_off + 16 * 80 + koff);
                LDSM_X4(alo[0], sb + WS_LO + a_off + koff);
                LDSM_X4(alo[1], sb + WS_LO + a_off + 16 * 80 + koff);

                uint32_t bh[7][2];
#pragma unroll
                for (int j = 0; j < 7; j++)
                    LDSM_X2(bh[j], sb + XS_HI + brow + j * 800 + koff);
#pragma unroll
                for (int j = 0; j < 7; j++) {
                    mma16816(acc[0][j], ahi[0], bh[j]);
                    mma16816(acc[1][j], ahi[1], bh[j]);
                    mma16816(acc[0][j], alo[0], bh[j]);
                    mma16816(acc[1][j], alo[1], bh[j]);
                }
                uint32_t bl[7][2];
#pragma unroll
                for (int j = 0; j < 7; j++)
                    LDSM_X2(bl[j], sb + XS_LO + brow + j * 800 + koff);
#pragma unroll
                for (int j = 0; j < 7; j++) {
                    mma16816(acc[0][j], ahi[0], bl[j]);
                    mma16816(acc[1][j], ahi[1], bl[j]);
                }
            }
            __syncthreads();   // protect W/X smem before restage
        }
    }

    // ---------------- epilogue ----------------
    // BN constants for the 4 co rows this thread owns
    float sc[2][2], bc[2][2];
#pragma unroll
    for (int t = 0; t < 2; t++)
#pragma unroll
        for (int hrow = 0; hrow < 2; hrow++) {
            int co = m0 + t * 16 + (lane >> 2) + hrow * 8;
            float s = gamma[co] * rsqrtf(var[co] + EPS);
            sc[t][hrow] = s;
            bc[t][hrow] = beta[co] - mean[co] * s;
        }

    if (MODE == 0) {
        __nv_bfloat16* eb = reinterpret_cast<__nv_bfloat16*>(smem);  // [112 q][128 co]
        for (int p = 0; p < 2; p++) {
            __syncthreads();
#pragma unroll
            for (int t = 0; t < 2; t++)
#pragma unroll
                for (int j = 0; j < 7; j++)
#pragma unroll
                    for (int e = 0; e < 4; e++) {
                        int hrow = e >> 1;
                        int co = m0 + t * 16 + (lane >> 2) + hrow * 8;
                        int q  = warpN * 56 + j * 8 + (lane & 3) * 2 + (e & 1);
                        float v = fmaxf(fmaf(acc[t][j][e], sc[t][hrow], bc[t][hrow]), 0.0f);
                        __nv_bfloat16 hv = __float2bfloat16(v);
                        __nv_bfloat16 ov = (p == 0) ? hv
                            : __float2bfloat16(v - __bfloat162float(hv));
                        eb[q * 128 + co] = ov;
                    }
            __syncthreads();
            __nv_bfloat16* gbase = p ? g_mlo : g_mhi;
            for (int i = tid; i < 1792; i += 256) {
                int q = i >> 4, seg = i & 15;
                uint4 v = reinterpret_cast<const uint4*>(eb)[i];
                *reinterpret_cast<uint4*>(gbase +
                    ((long)((n * 56 + h0 + (q & 7)) * 56 + c0 + (q >> 3))) * 128 + seg * 8) = v;
            }
        }
    } else {
        float* fs = reinterpret_cast<float*>(smem);   // [128 co][57]
        for (int win = 0; win < 2; win++) {
            __syncthreads();
            if (warpN == win) {
#pragma unroll
                for (int t = 0; t < 2; t++)
#pragma unroll
                    for (int j = 0; j < 7; j++)
#pragma unroll
                        for (int e = 0; e < 4; e++) {
                            int hrow = e >> 1;
                            int co = m0 + t * 16 + (lane >> 2) + hrow * 8;
                            int ql = j * 8 + (lane & 3) * 2 + (e & 1);
                            fs[co * 57 + ql] =
                                fmaf(acc[t][j][e], sc[t][hrow], bc[t][hrow]);
                        }
            }
            __syncthreads();
            for (int i = tid; i < 128 * 56; i += 256) {
                int co = i / 56, ql = i - co * 56;
                int c = ql >> 3, r = ql & 7;
                long g = ((long)(n * 128 + co) * 56 + h0 + r) * 56 + c0 + win * 7 + c;
                float v = fs[co * 57 + ql] + resid[g];
                outp[g] = fmaxf(v, 0.0f);
            }
        }
    }
}

extern "C" void kernel_launch(void* const* d_in, const int* in_sizes, int n_in,
                              void* d_out, int out_size)
{
    const float* x      = (const float*)d_in[0];
    const float* w1     = (const float*)d_in[1];
    const float* w2     = (const float*)d_in[2];
    const float* gamma1 = (const float*)d_in[3];
    const float* beta1  = (const float*)d_in[4];
    const float* mean1  = (const float*)d_in[5];
    const float* var1   = (const float*)d_in[6];
    const float* gamma2 = (const float*)d_in[7];
    const float* beta2  = (const float*)d_in[8];
    const float* mean2  = (const float*)d_in[9];
    const float* var2   = (const float*)d_in[10];
    float* out = (float*)d_out;

    prep_x<<<dim3(HHH, NB), 256>>>(x);
    prep_w<<<(2 * WT_ELEMS + 255) / 256, 256>>>(w1, w2);

    dim3 grid(4, 7, NB);   // 4 col-tiles x 7 row-bands x 64 images
    conv_mma<0><<<grid, 256, SMEM_BYTES>>>(gamma1, beta1, mean1, var1, nullptr, nullptr);
    conv_mma<1><<<grid, 256, SMEM_BYTES>>>(gamma2, beta2, mean2, var2, x, out);
}

// round 5
// speedup vs baseline: 3.6017x; 1.1523x over previous
#include <cuda_runtime.h>
#include <cuda_bf16.h>
#include <cstdint>
#include <math.h>

#define NB   64
#define HHH  56
#define WWW  56
#define EPS  1e-5f

// ---------------- global scratch (no cudaMalloc allowed) ----------------
#define NHWC_ELEMS (NB * HHH * WWW * 128)
__device__ __align__(16) __nv_bfloat16 g_xhi[NHWC_ELEMS];
__device__ __align__(16) __nv_bfloat16 g_xlo[NHWC_ELEMS];
__device__ __align__(16) __nv_bfloat16 g_mhi[NHWC_ELEMS];
__device__ __align__(16) __nv_bfloat16 g_mlo[NHWC_ELEMS];
#define WT_ELEMS (9 * 128 * 128)           // [tap][co][ci]
__device__ __align__(16) __nv_bfloat16 g_w1hi[WT_ELEMS];
__device__ __align__(16) __nv_bfloat16 g_w1lo[WT_ELEMS];
__device__ __align__(16) __nv_bfloat16 g_w2hi[WT_ELEMS];
__device__ __align__(16) __nv_bfloat16 g_w2lo[WT_ELEMS];

// ---------------- smem layout ----------------
// X slot: 160 rows (16 cols x 10 h) x 80B (32 ci + pad), hi then lo -> 25600 B. 2 slots.
// W slot: 128 co x 80B, hi then lo -> 20480 B. 3 slots.
#define X_PART     12800
#define X_SLOT     25600
#define W_PART     10240
#define W_SLOT     20480
#define WS_BASE    51200
#define SMEM_BYTES (WS_BASE + 3 * W_SLOT)   // 112640

__device__ __forceinline__ uint32_t smem_u32(const void* p) {
    uint32_t a;
    asm("{ .reg .u64 t; cvta.to.shared.u64 t, %1; cvt.u32.u64 %0, t; }" : "=r"(a) : "l"(p));
    return a;
}

__device__ __forceinline__ void cp16(uint32_t dst, const void* src, uint32_t sz) {
    asm volatile("cp.async.cg.shared.global [%0], [%1], 16, %2;"
                 :: "r"(dst), "l"(src), "r"(sz));
}
#define CP_COMMIT() asm volatile("cp.async.commit_group;" ::: "memory")
#define CP_WAIT1()  asm volatile("cp.async.wait_group 1;" ::: "memory")

#define LDSM_X4(r, addr)                                                       \
    asm volatile("ldmatrix.sync.aligned.m8n8.x4.shared.b16 {%0,%1,%2,%3}, [%4];" \
        : "=r"((r)[0]), "=r"((r)[1]), "=r"((r)[2]), "=r"((r)[3]) : "r"(addr))
#define LDSM_X2(r, addr)                                                       \
    asm volatile("ldmatrix.sync.aligned.m8n8.x2.shared.b16 {%0,%1}, [%2];"     \
        : "=r"((r)[0]), "=r"((r)[1]) : "r"(addr))

__device__ __forceinline__ void mma16816(float* d, const uint32_t* a, const uint32_t* b) {
    asm volatile(
        "mma.sync.aligned.m16n8k16.row.col.f32.bf16.bf16.f32 "
        "{%0,%1,%2,%3}, {%4,%5,%6,%7}, {%8,%9}, {%0,%1,%2,%3};"
        : "+f"(d[0]), "+f"(d[1]), "+f"(d[2]), "+f"(d[3])
        : "r"(a[0]), "r"(a[1]), "r"(a[2]), "r"(a[3]), "r"(b[0]), "r"(b[1]));
}

// ---- prep: NCHW fp32 x -> NHWC bf16 hi/lo ----
__global__ void prep_x(const float* __restrict__ x) {
    __shared__ float s[128][57];
    const int n = blockIdx.y, h = blockIdx.x;
    for (int i = threadIdx.x; i < 128 * 56; i += blockDim.x) {
        int ci = i / 56, w = i - ci * 56;
        s[ci][w] = x[((long)(n * 128 + ci) * 56 + h) * 56 + w];
    }
    __syncthreads();
    for (int i = threadIdx.x; i < 128 * 56; i += blockDim.x) {
        int w = i >> 7, ci = i & 127;
        float v = s[ci][w];
        __nv_bfloat16 hi = __float2bfloat16(v);
        __nv_bfloat16 lo = __float2bfloat16(v - __bfloat162float(hi));
        long idx = ((long)(n * 56 + h) * 56 + w) * 128 + ci;
        g_xhi[idx] = hi; g_xlo[idx] = lo;
    }
}

// ---- prep: OIHW fp32 w -> [tap][co][ci] bf16 hi/lo ----
__global__ void prep_w(const float* __restrict__ w1, const float* __restrict__ w2) {
    int i = blockIdx.x * blockDim.x + threadIdx.x;
    if (i >= 2 * WT_ELEMS) return;
    int conv = i / WT_ELEMS;
    int rem  = i - conv * WT_ELEMS;
    int tap  = rem >> 14;
    int co   = (rem >> 7) & 127;
    int ci   = rem & 127;
    int kh = tap / 3, kw = tap - kh * 3;
    const float* w = conv ? w2 : w1;
    float v = w[((co * 128 + ci) * 3 + kh) * 3 + kw];
    __nv_bfloat16 hi = __float2bfloat16(v);
    __nv_bfloat16 lo = __float2bfloat16(v - __bfloat162float(hi));
    if (conv) { g_w2hi[rem] = hi; g_w2lo[rem] = lo; }
    else      { g_w1hi[rem] = hi; g_w1lo[rem] = lo; }
}

// MODE 0: src g_x*, w1, BN1, relu -> g_m* (NHWC bf16 hi/lo)
// MODE 1: src g_m*, w2, BN2, +x(NCHW), relu -> out (NCHW fp32)
template <int MODE>
__global__ void __launch_bounds__(256)
conv_mma(const float* __restrict__ gamma, const float* __restrict__ beta,
         const float* __restrict__ mean,  const float* __restrict__ var,
         const float* __restrict__ resid, float* __restrict__ outp)
{
    extern __shared__ char smem[];
    const uint32_t sb = smem_u32(smem);
    const int tid  = threadIdx.x;
    const int lane = tid & 31;
    const int wid  = tid >> 5;
    const int warpM = wid & 3;        // co tile of 32
    const int warpN = wid >> 2;       // q tile of 56
    const int n  = blockIdx.z;
    const int h0 = blockIdx.y * 8;
    const int c0 = blockIdx.x * 14;

    const __nv_bfloat16* shi = (MODE == 0) ? g_xhi : g_mhi;
    const __nv_bfloat16* slo = (MODE == 0) ? g_xlo : g_mlo;
    const __nv_bfloat16* whi = (MODE == 0) ? g_w1hi : g_w2hi;
    const __nv_bfloat16* wlo = (MODE == 0) ? g_w1lo : g_w2lo;

    // ---- async stage helpers (lambdas over tid) ----
    auto stage_x = [&](int chunk) {
        const int ci0 = chunk * 32;
        const uint32_t xb = sb + (uint32_t)(chunk & 1) * X_SLOT;
        for (int i = tid; i < 1280; i += 256) {
            int p   = i >> 9 >= 1 ? (i >= 640) : 0;   // i<640 -> hi, else lo
            p = (i >= 640);
            int rem = p ? i - 640 : i;
            int row = rem >> 2, seg = rem & 3;
            int cx = row / 10, rh = row - cx * 10;
            int h = h0 + rh - 1, w = c0 + cx - 1;
            bool ok = ((unsigned)h < 56u) && ((unsigned)w < 56u);
            const __nv_bfloat16* src = p ? slo : shi;
            long gi = (((long)(n * 56 + (ok ? h : 0)) * 56 + (ok ? w : 0)) * 128 + ci0 + seg * 8);
            cp16(xb + (uint32_t)p * X_PART + row * 80 + seg * 16, src + gi, ok ? 16u : 0u);
        }
    };
    auto stage_w = [&](int gt) {
        const int chunk = gt / 9, tap = gt - chunk * 9;
        const int ci0 = chunk * 32;
        const uint32_t wb = sb + WS_BASE + (uint32_t)(gt % 3) * W_SLOT;
        for (int i = tid; i < 1024; i += 256) {
            int p   = (i >= 512);
            int rem = p ? i - 512 : i;
            int co = rem >> 2, seg = rem & 3;
            const __nv_bfloat16* src = p ? wlo : whi;
            cp16(wb + (uint32_t)p * W_PART + co * 80 + seg * 16,
                 src + (long)tap * 16384 + co * 128 + ci0 + seg * 8, 16u);
        }
    };

    float acc[2][7][4];
#pragma unroll
    for (int t = 0; t < 2; t++)
#pragma unroll
        for (int j = 0; j < 7; j++)
#pragma unroll
            for (int e = 0; e < 4; e++)
                acc[t][j][e] = 0.0f;

    const int m0 = warpM * 32;
    const uint32_t a_off = (uint32_t)(m0 + (lane & 15)) * 80 + ((lane >> 4) & 1) * 16;
    const uint32_t b_lane_off = (uint32_t)(lane & 7) * 80 + ((lane >> 3) & 1) * 16;

    // ---- prologue: 2 groups in flight ----
    stage_x(0); stage_w(0); CP_COMMIT();
    stage_x(1); stage_w(1); CP_COMMIT();

    for (int gt = 0; gt < 36; gt++) {
        CP_WAIT1();
        __syncthreads();
        // prefetch (exactly one commit per iteration)
        if (gt + 2 < 36) stage_w(gt + 2);
        if ((gt % 9) == 0) {
            int nc = gt / 9 + 1;
            if (nc >= 2 && nc < 4) stage_x(nc);
        }
        CP_COMMIT();

        const int chunk = gt / 9, tap = gt - chunk * 9;
        const int kh = tap / 3, kw = tap - kh * 3;
        const uint32_t xb = sb + (uint32_t)(chunk & 1) * X_SLOT;
        const uint32_t wb = sb + WS_BASE + (uint32_t)(gt % 3) * W_SLOT;
        const uint32_t brow = (uint32_t)((warpN * 7 + kw) * 10 + kh) * 80 + b_lane_off;

#pragma unroll
        for (int k16 = 0; k16 < 2; k16++) {
            const uint32_t koff = k16 * 32;
            uint32_t ahi[2][4], alo[2][4];
            LDSM_X4(ahi[0], wb + a_off + koff);
            LDSM_X4(ahi[1], wb + a_off + 16 * 80 + koff);
            LDSM_X4(alo[0], wb + W_PART + a_off + koff);
            LDSM_X4(alo[1], wb + W_PART + a_off + 16 * 80 + koff);

            uint32_t bh[7][2];
#pragma unroll
            for (int j = 0; j < 7; j++)
                LDSM_X2(bh[j], xb + brow + j * 800 + koff);
#pragma unroll
            for (int j = 0; j < 7; j++) {
                mma16816(acc[0][j], ahi[0], bh[j]);
                mma16816(acc[1][j], ahi[1], bh[j]);
                mma16816(acc[0][j], alo[0], bh[j]);
                mma16816(acc[1][j], alo[1], bh[j]);
            }
            uint32_t bl[7][2];
#pragma unroll
            for (int j = 0; j < 7; j++)
                LDSM_X2(bl[j], xb + X_PART + brow + j * 800 + koff);
#pragma unroll
            for (int j = 0; j < 7; j++) {
                mma16816(acc[0][j], ahi[0], bl[j]);
                mma16816(acc[1][j], ahi[1], bl[j]);
            }
        }
    }

    // ---------------- epilogue ----------------
    float sc[2][2], bc[2][2];
#pragma unroll
    for (int t = 0; t < 2; t++)
#pragma unroll
        for (int hrow = 0; hrow < 2; hrow++) {
            int co = m0 + t * 16 + (lane >> 2) + hrow * 8;
            float s = gamma[co] * rsqrtf(var[co] + EPS);
            sc[t][hrow] = s;
            bc[t][hrow] = beta[co] - mean[co] * s;
        }

    if (MODE == 0) {
        __nv_bfloat16* eb = reinterpret_cast<__nv_bfloat16*>(smem);  // [112 q][128 co]
        for (int p = 0; p < 2; p++) {
            __syncthreads();
#pragma unroll
            for (int t = 0; t < 2; t++)
#pragma unroll
                for (int j = 0; j < 7; j++)
#pragma unroll
                    for (int e = 0; e < 4; e++) {
                        int hrow = e >> 1;
                        int co = m0 + t * 16 + (lane >> 2) + hrow * 8;
                        int q  = warpN * 56 + j * 8 + (lane & 3) * 2 + (e & 1);
                        float v = fmaxf(fmaf(acc[t][j][e], sc[t][hrow], bc[t][hrow]), 0.0f);
                        __nv_bfloat16 hv = __float2bfloat16(v);
                        __nv_bfloat16 ov = (p == 0) ? hv
                            : __float2bfloat16(v - __bfloat162float(hv));
                        eb[q * 128 + co] = ov;
                    }
            __syncthreads();
            __nv_bfloat16* gbase = p ? g_mlo : g_mhi;
            for (int i = tid; i < 1792; i += 256) {
                int q = i >> 4, seg = i & 15;
                uint4 v = reinterpret_cast<const uint4*>(eb)[i];
                *reinterpret_cast<uint4*>(gbase +
                    ((long)((n * 56 + h0 + (q & 7)) * 56 + c0 + (q >> 3))) * 128 + seg * 8) = v;
            }
        }
    } else {
        float* fs = reinterpret_cast<float*>(smem);   // [128 co][57]
        for (int win = 0; win < 2; win++) {
            __syncthreads();
            if (warpN == win) {
#pragma unroll
                for (int t = 0; t < 2; t++)
#pragma unroll
                    for (int j = 0; j < 7; j++)
#pragma unroll
                        for (int e = 0; e < 4; e++) {
                            int hrow = e >> 1;
                            int co = m0 + t * 16 + (lane >> 2) + hrow * 8;
                            int ql = j * 8 + (lane & 3) * 2 + (e & 1);
                            fs[co * 57 + ql] =
                                fmaf(acc[t][j][e], sc[t][hrow], bc[t][hrow]);
                        }
            }
            __syncthreads();
            for (int i = tid; i < 128 * 56; i += 256) {
                int co = i / 56, ql = i - co * 56;
                int c = ql >> 3, r = ql & 7;
                long g = ((long)(n * 128 + co) * 56 + h0 + r) * 56 + c0 + win * 7 + c;
                float v = fs[co * 57 + ql] + resid[g];
                outp[g] = fmaxf(v, 0.0f);
            }
        }
    }
}

extern "C" void kernel_launch(void* const* d_in, const int* in_sizes, int n_in,
                              void* d_out, int out_size)
{
    const float* x      = (const float*)d_in[0];
    const float* w1     = (const float*)d_in[1];
    const float* w2     = (const float*)d_in[2];
    const float* gamma1 = (const float*)d_in[3];
    const float* beta1  = (const float*)d_in[4];
    const float* mean1  = (const float*)d_in[5];
    const float* var1   = (const float*)d_in[6];
    const float* gamma2 = (const float*)d_in[7];
    const float* beta2  = (const float*)d_in[8];
    const float* mean2  = (const float*)d_in[9];
    const float* var2   = (const float*)d_in[10];
    float* out = (float*)d_out;

    cudaFuncSetAttribute(conv_mma<0>, cudaFuncAttributeMaxDynamicSharedMemorySize, SMEM_BYTES);
    cudaFuncSetAttribute(conv_mma<1>, cudaFuncAttributeMaxDynamicSharedMemorySize, SMEM_BYTES);

    prep_x<<<dim3(HHH, NB), 256>>>(x);
    prep_w<<<(2 * WT_ELEMS + 255) / 256, 256>>>(w1, w2);

    dim3 grid(4, 7, NB);   // 4 col-tiles x 7 row-bands x 64 images
    conv_mma<0><<<grid, 256, SMEM_BYTES>>>(gamma1, beta1, mean1, var1, nullptr, nullptr);
    conv_mma<1><<<grid, 256, SMEM_BYTES>>>(gamma2, beta2, mean2, var2, x, out);
}

// round 6
// speedup vs baseline: 4.5056x; 1.2510x over previous
#include <cuda_runtime.h>
#include <cuda_bf16.h>
#include <cstdint>
#include <math.h>

#define NB   64
#define HHH  56
#define WWW  56
#define EPS  1e-5f

// ---------------- global scratch (no cudaMalloc allowed) ----------------
#define NHWC_ELEMS (NB * HHH * WWW * 128)
__device__ __align__(16) __nv_bfloat16 g_xhi[NHWC_ELEMS];
__device__ __align__(16) __nv_bfloat16 g_xlo[NHWC_ELEMS];
__device__ __align__(16) __nv_bfloat16 g_mhi[NHWC_ELEMS];
__device__ __align__(16) __nv_bfloat16 g_mlo[NHWC_ELEMS];

// W in fragment-major layout: [conv][part][ ((tap*8 + mtile)*8 + k16g)*128 + lane*4 + r ]
// Each lane's 4 regs for one m16k16 A-fragment are 16B contiguous -> LDG.128.
#define WF_U32 (9 * 8 * 8 * 128)     // 73728 uint32 per conv per part
__device__ __align__(16) uint32_t g_wf[2][2][WF_U32];

// ---------------- smem: 2 X slots only ----------------
// X slot: 160 rows (16 cols x 10 h) x 80B, hi then lo.
#define X_PART     12800
#define X_SLOT     25600
#define SMEM_BYTES (2 * X_SLOT)      // 51200

__device__ __forceinline__ uint32_t smem_u32(const void* p) {
    uint32_t a;
    asm("{ .reg .u64 t; cvta.to.shared.u64 t, %1; cvt.u32.u64 %0, t; }" : "=r"(a) : "l"(p));
    return a;
}
__device__ __forceinline__ void cp16(uint32_t dst, const void* src, uint32_t sz) {
    asm volatile("cp.async.cg.shared.global [%0], [%1], 16, %2;"
                 :: "r"(dst), "l"(src), "r"(sz));
}
#define CP_COMMIT() asm volatile("cp.async.commit_group;" ::: "memory")
#define CP_WAIT0()  asm volatile("cp.async.wait_group 0;" ::: "memory")

#define LDSM_X2(r, addr)                                                       \
    asm volatile("ldmatrix.sync.aligned.m8n8.x2.shared.b16 {%0,%1}, [%2];"     \
        : "=r"((r)[0]), "=r"((r)[1]) : "r"(addr))

__device__ __forceinline__ void mma16816(float* d, const uint32_t* a, const uint32_t* b) {
    asm volatile(
        "mma.sync.aligned.m16n8k16.row.col.f32.bf16.bf16.f32 "
        "{%0,%1,%2,%3}, {%4,%5,%6,%7}, {%8,%9}, {%0,%1,%2,%3};"
        : "+f"(d[0]), "+f"(d[1]), "+f"(d[2]), "+f"(d[3])
        : "r"(a[0]), "r"(a[1]), "r"(a[2]), "r"(a[3]), "r"(b[0]), "r"(b[1]));
}

// ---- prep: NCHW fp32 x -> NHWC bf16 hi/lo ----
__global__ void prep_x(const float* __restrict__ x) {
    __shared__ float s[128][57];
    const int n = blockIdx.y, h = blockIdx.x;
    for (int i = threadIdx.x; i < 128 * 56; i += blockDim.x) {
        int ci = i / 56, w = i - ci * 56;
        s[ci][w] = x[((long)(n * 128 + ci) * 56 + h) * 56 + w];
    }
    __syncthreads();
    for (int i = threadIdx.x; i < 128 * 56; i += blockDim.x) {
        int w = i >> 7, ci = i & 127;
        float v = s[ci][w];
        __nv_bfloat16 hi = __float2bfloat16(v);
        __nv_bfloat16 lo = __float2bfloat16(v - __bfloat162float(hi));
        long idx = ((long)(n * 56 + h) * 56 + w) * 128 + ci;
        g_xhi[idx] = hi; g_xlo[idx] = lo;
    }
}

// ---- prep: OIHW fp32 w -> fragment-major bf16 hi/lo ----
// m16n8k16 A-fragment mapping (row-major A):
//   r=0: (co_b, ci_b)  r=1: (co_b+8, ci_b)  r=2: (co_b, ci_b+8)  r=3: (co_b+8, ci_b+8)
//   co_b = mt*16 + (lane>>2), ci_b = kg*16 + (lane&3)*2   (each u32 = 2 consecutive ci)
__global__ void prep_w(const float* __restrict__ w1, const float* __restrict__ w2) {
    int i = blockIdx.x * blockDim.x + threadIdx.x;
    if (i >= 4 * WF_U32) return;
    int conv = i / (2 * WF_U32);
    int rem  = i - conv * (2 * WF_U32);
    int part = rem / WF_U32;
    int r2   = rem - part * WF_U32;
    int tap  = r2 >> 13;
    int r3   = r2 & 8191;
    int mt   = r3 >> 10;
    int r4   = r3 & 1023;
    int kg   = r4 >> 7;
    int r5   = r4 & 127;
    int lane = r5 >> 2;
    int r    = r5 & 3;
    int co = mt * 16 + (lane >> 2) + (r & 1) * 8;
    int ci = kg * 16 + (lane & 3) * 2 + (r >> 1) * 8;
    int kh = tap / 3, kw = tap - kh * 3;
    const float* w = conv ? w2 : w1;
    float v0 = w[((co * 128 + ci) * 3 + kh) * 3 + kw];
    float v1 = w[((co * 128 + ci + 1) * 3 + kh) * 3 + kw];
    __nv_bfloat16 h0 = __float2bfloat16(v0);
    __nv_bfloat16 h1 = __float2bfloat16(v1);
    uint32_t out;
    if (part == 0) {
        out = (uint32_t)__bfloat16_as_ushort(h0) |
              ((uint32_t)__bfloat16_as_ushort(h1) << 16);
    } else {
        __nv_bfloat16 l0 = __float2bfloat16(v0 - __bfloat162float(h0));
        __nv_bfloat16 l1 = __float2bfloat16(v1 - __bfloat162float(h1));
        out = (uint32_t)__bfloat16_as_ushort(l0) |
              ((uint32_t)__bfloat16_as_ushort(l1) << 16);
    }
    g_wf[conv][part][r2] = out;
}

// MODE 0: src g_x*, w1, BN1, relu -> g_m* (NHWC bf16 hi/lo)
// MODE 1: src g_m*, w2, BN2, +x(NCHW), relu -> out (NCHW fp32)
template <int MODE>
__global__ void __launch_bounds__(256, 2)
conv_mma(const float* __restrict__ gamma, const float* __restrict__ beta,
         const float* __restrict__ mean,  const float* __restrict__ var,
         const float* __restrict__ resid, float* __restrict__ outp)
{
    extern __shared__ char smem[];
    const uint32_t sb = smem_u32(smem);
    const int tid  = threadIdx.x;
    const int lane = tid & 31;
    const int wid  = tid >> 5;
    const int warpM = wid & 3;        // co tile of 32
    const int warpN = wid >> 2;       // q tile of 56
    const int n  = blockIdx.z;
    const int h0 = blockIdx.y * 8;
    const int c0 = blockIdx.x * 14;

    const __nv_bfloat16* shi = (MODE == 0) ? g_xhi : g_mhi;
    const __nv_bfloat16* slo = (MODE == 0) ? g_xlo : g_mlo;
    const uint32_t* wfh = &g_wf[MODE][0][(size_t)(warpM * 2) * 1024 + lane * 4];
    const uint32_t* wfl = &g_wf[MODE][1][(size_t)(warpM * 2) * 1024 + lane * 4];

    auto stage_x = [&](int chunk) {
        const int ci0 = chunk * 32;
        const uint32_t xb = sb + (uint32_t)(chunk & 1) * X_SLOT;
        for (int i = tid; i < 1280; i += 256) {
            int p   = (i >= 640);
            int rem = i - p * 640;
            int row = rem >> 2, seg = rem & 3;
            int cx = row / 10, rh = row - cx * 10;
            int h = h0 + rh - 1, w = c0 + cx - 1;
            bool ok = ((unsigned)h < 56u) && ((unsigned)w < 56u);
            const __nv_bfloat16* src = p ? slo : shi;
            long gi = (((long)(n * 56 + (ok ? h : 0)) * 56 + (ok ? w : 0)) * 128
                       + ci0 + seg * 8);
            cp16(xb + (uint32_t)p * X_PART + row * 80 + seg * 16, src + gi, ok ? 16u : 0u);
        }
    };

    float acc[2][7][4];
#pragma unroll
    for (int t = 0; t < 2; t++)
#pragma unroll
        for (int j = 0; j < 7; j++)
#pragma unroll
            for (int e = 0; e < 4; e++)
                acc[t][j][e] = 0.0f;

    const int m0 = warpM * 32;
    const uint32_t b_lane_off = (uint32_t)(lane & 7) * 80 + ((lane >> 3) & 1) * 16;

    stage_x(0); CP_COMMIT();

#pragma unroll 1
    for (int chunk = 0; chunk < 4; chunk++) {
        CP_WAIT0();
        __syncthreads();
        if (chunk < 3) { stage_x(chunk + 1); CP_COMMIT(); }

        const uint32_t xb = sb + (uint32_t)(chunk & 1) * X_SLOT;
#pragma unroll 1
        for (int tap = 0; tap < 9; tap++) {
            const int kh = tap / 3, kw = tap - kh * 3;
            const uint32_t brow =
                (uint32_t)((warpN * 7 + kw) * 10 + kh) * 80 + b_lane_off;
            const int wtap = tap * 8192;
#pragma unroll
            for (int k16 = 0; k16 < 2; k16++) {
                const int woff = wtap + (chunk * 2 + k16) * 128;
                uint32_t ahi[2][4], alo[2][4];
                *reinterpret_cast<uint4*>(ahi[0]) =
                    *reinterpret_cast<const uint4*>(wfh + woff);
                *reinterpret_cast<uint4*>(ahi[1]) =
                    *reinterpret_cast<const uint4*>(wfh + woff + 1024);
                *reinterpret_cast<uint4*>(alo[0]) =
                    *reinterpret_cast<const uint4*>(wfl + woff);
                *reinterpret_cast<uint4*>(alo[1]) =
                    *reinterpret_cast<const uint4*>(wfl + woff + 1024);

                const uint32_t koff = k16 * 32;
                uint32_t bh[7][2];
#pragma unroll
                for (int j = 0; j < 7; j++)
                    LDSM_X2(bh[j], xb + brow + j * 800 + koff);
#pragma unroll
                for (int j = 0; j < 7; j++) {
                    mma16816(acc[0][j], ahi[0], bh[j]);
                    mma16816(acc[1][j], ahi[1], bh[j]);
                    mma16816(acc[0][j], alo[0], bh[j]);
                    mma16816(acc[1][j], alo[1], bh[j]);
                }
                uint32_t bl[7][2];
#pragma unroll
                for (int j = 0; j < 7; j++)
                    LDSM_X2(bl[j], xb + X_PART + brow + j * 800 + koff);
#pragma unroll
                for (int j = 0; j < 7; j++) {
                    mma16816(acc[0][j], ahi[0], bl[j]);
                    mma16816(acc[1][j], ahi[1], bl[j]);
                }
            }
        }
    }

    // ---------------- epilogue ----------------
    float sc[2][2], bc[2][2];
#pragma unroll
    for (int t = 0; t < 2; t++)
#pragma unroll
        for (int hrow = 0; hrow < 2; hrow++) {
            int co = m0 + t * 16 + (lane >> 2) + hrow * 8;
            float s = gamma[co] * rsqrtf(var[co] + EPS);
            sc[t][hrow] = s;
            bc[t][hrow] = beta[co] - mean[co] * s;
        }

    if (MODE == 0) {
        __nv_bfloat16* eb = reinterpret_cast<__nv_bfloat16*>(smem);  // [112 q][128 co]
        for (int p = 0; p < 2; p++) {
            __syncthreads();
#pragma unroll
            for (int t = 0; t < 2; t++)
#pragma unroll
                for (int j = 0; j < 7; j++)
#pragma unroll
                    for (int e = 0; e < 4; e++) {
                        int hrow = e >> 1;
                        int co = m0 + t * 16 + (lane >> 2) + hrow * 8;
                        int q  = warpN * 56 + j * 8 + (lane & 3) * 2 + (e & 1);
                        float v = fmaxf(fmaf(acc[t][j][e], sc[t][hrow], bc[t][hrow]), 0.0f);
                        __nv_bfloat16 hv = __float2bfloat16(v);
                        __nv_bfloat16 ov = (p == 0) ? hv
                            : __float2bfloat16(v - __bfloat162float(hv));
                        eb[q * 128 + co] = ov;
                    }
            __syncthreads();
            __nv_bfloat16* gbase = p ? g_mlo : g_mhi;
            for (int i = tid; i < 1792; i += 256) {
                int q = i >> 4, seg = i & 15;
                uint4 v = reinterpret_cast<const uint4*>(eb)[i];
                *reinterpret_cast<uint4*>(gbase +
                    ((long)((n * 56 + h0 + (q & 7)) * 56 + c0 + (q >> 3))) * 128 + seg * 8) = v;
            }
        }
    } else {
        float* fs = reinterpret_cast<float*>(smem);   // [128 co][57]
        for (int win = 0; win < 2; win++) {
            __syncthreads();
            if (warpN == win) {
#pragma unroll
                for (int t = 0; t < 2; t++)
#pragma unroll
                    for (int j = 0; j < 7; j++)
#pragma unroll
                        for (int e = 0; e < 4; e++) {
                            int hrow = e >> 1;
                            int co = m0 + t * 16 + (lane >> 2) + hrow * 8;
                            int ql = j * 8 + (lane & 3) * 2 + (e & 1);
                            fs[co * 57 + ql] =
                                fmaf(acc[t][j][e], sc[t][hrow], bc[t][hrow]);
                        }
            }
            __syncthreads();
            for (int i = tid; i < 128 * 56; i += 256) {
                int co = i / 56, ql = i - co * 56;
                int c = ql >> 3, r = ql & 7;
                long g = ((long)(n * 128 + co) * 56 + h0 + r) * 56 + c0 + win * 7 + c;
                float v = fs[co * 57 + ql] + resid[g];
                outp[g] = fmaxf(v, 0.0f);
            }
        }
    }
}

extern "C" void kernel_launch(void* const* d_in, const int* in_sizes, int n_in,
                              void* d_out, int out_size)
{
    const float* x      = (const float*)d_in[0];
    const float* w1     = (const float*)d_in[1];
    const float* w2     = (const float*)d_in[2];
    const float* gamma1 = (const float*)d_in[3];
    const float* beta1  = (const float*)d_in[4];
    const float* mean1  = (const float*)d_in[5];
    const float* var1   = (const float*)d_in[6];
    const float* gamma2 = (const float*)d_in[7];
    const float* beta2  = (const float*)d_in[8];
    const float* mean2  = (const float*)d_in[9];
    const float* var2   = (const float*)d_in[10];
    float* out = (float*)d_out;

    cudaFuncSetAttribute(conv_mma<0>, cudaFuncAttributeMaxDynamicSharedMemorySize, SMEM_BYTES);
    cudaFuncSetAttribute(conv_mma<1>, cudaFuncAttributeMaxDynamicSharedMemorySize, SMEM_BYTES);

    prep_x<<<dim3(HHH, NB), 256>>>(x);
    prep_w<<<(4 * WF_U32 + 255) / 256, 256>>>(w1, w2);

    dim3 grid(4, 7, NB);   // 4 col-tiles x 7 row-bands x 64 images
    conv_mma<0><<<grid, 256, SMEM_BYTES>>>(gamma1, beta1, mean1, var1, nullptr, nullptr);
    conv_mma<1><<<grid, 256, SMEM_BYTES>>>(gamma2, beta2, mean2, var2, x, out);
}

// round 7
// speedup vs baseline: 9.0683x; 2.0127x over previous
#include <cuda_runtime.h>
#include <cuda_fp16.h>
#include <cstdint>
#include <math.h>

#define NB   64
#define HHH  56
#define WWW  56
#define EPS  1e-5f

// ---------------- global scratch (no cudaMalloc allowed) ----------------
#define NHWC_ELEMS (NB * HHH * WWW * 128)
__device__ __align__(16) __half g_xf[NHWC_ELEMS];
__device__ __align__(16) __half g_mf[NHWC_ELEMS];

// W fragment-major: [conv][ ((tap*8 + mtile)*8 + kg)*128 + lane*4 + r ], fp16 pairs.
#define WF_U32 (9 * 8 * 8 * 128)
__device__ __align__(16) uint32_t g_wf[2][WF_U32];

// ---------------- smem ----------------
// X slot: 160 rows (16 cols x 10 h) x 80B (32 ci fp16 = 64B + 16 pad). 2 slots.
#define X_SLOT     12800
#define SMEM_BYTES 29184   // max(2*X_SLOT=25600, MODE0 eb=28672, MODE1 fs=29184)

__device__ __forceinline__ uint32_t smem_u32(const void* p) {
    uint32_t a;
    asm("{ .reg .u64 t; cvta.to.shared.u64 t, %1; cvt.u32.u64 %0, t; }" : "=r"(a) : "l"(p));
    return a;
}
__device__ __forceinline__ void cp16(uint32_t dst, const void* src, uint32_t sz) {
    asm volatile("cp.async.cg.shared.global [%0], [%1], 16, %2;"
                 :: "r"(dst), "l"(src), "r"(sz));
}
#define CP_COMMIT() asm volatile("cp.async.commit_group;" ::: "memory")
#define CP_WAIT0()  asm volatile("cp.async.wait_group 0;" ::: "memory")

#define LDSM_X4(r, addr)                                                       \
    asm volatile("ldmatrix.sync.aligned.m8n8.x4.shared.b16 {%0,%1,%2,%3}, [%4];" \
        : "=r"((r)[0]), "=r"((r)[1]), "=r"((r)[2]), "=r"((r)[3]) : "r"(addr))

__device__ __forceinline__ void mma16816(float* d, const uint32_t* a, const uint32_t* b) {
    asm volatile(
        "mma.sync.aligned.m16n8k16.row.col.f32.f16.f16.f32 "
        "{%0,%1,%2,%3}, {%4,%5,%6,%7}, {%8,%9}, {%0,%1,%2,%3};"
        : "+f"(d[0]), "+f"(d[1]), "+f"(d[2]), "+f"(d[3])
        : "r"(a[0]), "r"(a[1]), "r"(a[2]), "r"(a[3]), "r"(b[0]), "r"(b[1]));
}

// ---- prep: NCHW fp32 x -> NHWC fp16 ----
__global__ void prep_x(const float* __restrict__ x) {
    __shared__ float s[128][57];
    const int n = blockIdx.y, h = blockIdx.x;
    for (int i = threadIdx.x; i < 128 * 56; i += blockDim.x) {
        int ci = i / 56, w = i - ci * 56;
        s[ci][w] = x[((long)(n * 128 + ci) * 56 + h) * 56 + w];
    }
    __syncthreads();
    for (int i = threadIdx.x; i < 128 * 56; i += blockDim.x) {
        int w = i >> 7, ci = i & 127;
        long idx = ((long)(n * 56 + h) * 56 + w) * 128 + ci;
        g_xf[idx] = __float2half(s[ci][w]);
    }
}

// ---- prep: OIHW fp32 w -> fragment-major fp16 ----
// m16n8k16 A-fragment: r=0:(co_b,ci_b) r=1:(co_b+8,ci_b) r=2:(co_b,ci_b+8) r=3:(co_b+8,ci_b+8)
//   co_b = mt*16 + (lane>>2), ci_b = kg*16 + (lane&3)*2
__global__ void prep_w(const float* __restrict__ w1, const float* __restrict__ w2) {
    int i = blockIdx.x * blockDim.x + threadIdx.x;
    if (i >= 2 * WF_U32) return;
    int conv = i / WF_U32;
    int r2   = i - conv * WF_U32;
    int tap  = r2 >> 13;
    int mt   = (r2 >> 10) & 7;
    int kg   = (r2 >> 7) & 7;
    int lane = (r2 >> 2) & 31;
    int r    = r2 & 3;
    int co = mt * 16 + (lane >> 2) + (r & 1) * 8;
    int ci = kg * 16 + (lane & 3) * 2 + (r >> 1) * 8;
    int kh = tap / 3, kw = tap - kh * 3;
    const float* w = conv ? w2 : w1;
    __half h0 = __float2half(w[((co * 128 + ci) * 3 + kh) * 3 + kw]);
    __half h1 = __float2half(w[((co * 128 + ci + 1) * 3 + kh) * 3 + kw]);
    g_wf[conv][r2] = (uint32_t)__half_as_ushort(h0) |
                     ((uint32_t)__half_as_ushort(h1) << 16);
}

// MODE 0: src g_xf, w1, BN1, relu -> g_mf (NHWC fp16)
// MODE 1: src g_mf, w2, BN2, +x(NCHW), relu -> out (NCHW fp32)
template <int MODE>
__global__ void __launch_bounds__(256, 2)
conv_mma(const float* __restrict__ gamma, const float* __restrict__ beta,
         const float* __restrict__ mean,  const float* __restrict__ var,
         const float* __restrict__ resid, float* __restrict__ outp)
{
    extern __shared__ char smem[];
    const uint32_t sb = smem_u32(smem);
    const int tid  = threadIdx.x;
    const int lane = tid & 31;
    const int wid  = tid >> 5;
    const int warpM = wid & 3;
    const int warpN = wid >> 2;
    const int n  = blockIdx.z;
    const int h0 = blockIdx.y * 8;
    const int c0 = blockIdx.x * 14;

    const __half* src = (MODE == 0) ? g_xf : g_mf;
    const uint32_t* wf = &g_wf[MODE][(size_t)(warpM * 2) * 1024 + lane * 4];

    auto stage_x = [&](int chunk) {
        const int ci0 = chunk * 32;
        const uint32_t xb = sb + (uint32_t)(chunk & 1) * X_SLOT;
        for (int i = tid; i < 640; i += 256) {
            int row = i >> 2, seg = i & 3;
            int cx = row / 10, rh = row - cx * 10;
            int h = h0 + rh - 1, w = c0 + cx - 1;
            bool ok = ((unsigned)h < 56u) && ((unsigned)w < 56u);
            long gi = (((long)(n * 56 + (ok ? h : 0)) * 56 + (ok ? w : 0)) * 128
                       + ci0 + seg * 8);
            cp16(xb + row * 80 + seg * 16, src + gi, ok ? 16u : 0u);
        }
    };

    float acc[2][7][4];
#pragma unroll
    for (int t = 0; t < 2; t++)
#pragma unroll
        for (int j = 0; j < 7; j++)
#pragma unroll
            for (int e = 0; e < 4; e++)
                acc[t][j][e] = 0.0f;

    const int m0 = warpM * 32;
    // x4 ldmatrix: 4 lane-groups address the 4 ci segments (both k16 halves)
    const uint32_t b_off4 = (uint32_t)(lane & 7) * 80 + ((lane >> 3) & 3) * 16;

    stage_x(0); CP_COMMIT();

#pragma unroll 1
    for (int chunk = 0; chunk < 4; chunk++) {
        CP_WAIT0();
        __syncthreads();
        if (chunk < 3) { stage_x(chunk + 1); CP_COMMIT(); }

        const uint32_t xb = sb + (uint32_t)(chunk & 1) * X_SLOT;
#pragma unroll 1
        for (int tap = 0; tap < 9; tap++) {
            const int kh = tap / 3, kw = tap - kh * 3;
            const uint32_t brow =
                (uint32_t)((warpN * 7 + kw) * 10 + kh) * 80 + b_off4;

            uint32_t a[2][2][4];   // [k16][mtile]
#pragma unroll
            for (int k16 = 0; k16 < 2; k16++)
#pragma unroll
                for (int mt = 0; mt < 2; mt++)
                    *reinterpret_cast<uint4*>(a[k16][mt]) =
                        *reinterpret_cast<const uint4*>(
                            wf + tap * 8192 + mt * 1024 + (chunk * 2 + k16) * 128);

            uint32_t bq[7][4];
#pragma unroll
            for (int j = 0; j < 7; j++)
                LDSM_X4(bq[j], xb + brow + j * 800);
#pragma unroll
            for (int j = 0; j < 7; j++) {
                mma16816(acc[0][j], a[0][0], bq[j]);
                mma16816(acc[1][j], a[0][1], bq[j]);
                mma16816(acc[0][j], a[1][0], bq[j] + 2);
                mma16816(acc[1][j], a[1][1], bq[j] + 2);
            }
        }
    }

    // ---------------- epilogue ----------------
    float sc[2][2], bc[2][2];
#pragma unroll
    for (int t = 0; t < 2; t++)
#pragma unroll
        for (int hrow = 0; hrow < 2; hrow++) {
            int co = m0 + t * 16 + (lane >> 2) + hrow * 8;
            float s = gamma[co] * rsqrtf(var[co] + EPS);
            sc[t][hrow] = s;
            bc[t][hrow] = beta[co] - mean[co] * s;
        }

    if (MODE == 0) {
        __half* eb = reinterpret_cast<__half*>(smem);   // [112 q][128 co]
        __syncthreads();
#pragma unroll
        for (int t = 0; t < 2; t++)
#pragma unroll
            for (int j = 0; j < 7; j++)
#pragma unroll
                for (int e = 0; e < 4; e++) {
                    int hrow = e >> 1;
                    int co = m0 + t * 16 + (lane >> 2) + hrow * 8;
                    int q  = warpN * 56 + j * 8 + (lane & 3) * 2 + (e & 1);
                    float v = fmaxf(fmaf(acc[t][j][e], sc[t][hrow], bc[t][hrow]), 0.0f);
                    eb[q * 128 + co] = __float2half(v);
                }
        __syncthreads();
        for (int i = tid; i < 1792; i += 256) {
            int q = i >> 4, seg = i & 15;
            uint4 v = reinterpret_cast<const uint4*>(eb)[i];
            *reinterpret_cast<uint4*>(g_mf +
                ((long)((n * 56 + h0 + (q & 7)) * 56 + c0 + (q >> 3))) * 128 + seg * 8) = v;
        }
    } else {
        float* fs = reinterpret_cast<float*>(smem);   // [128 co][57]
        for (int win = 0; win < 2; win++) {
            __syncthreads();
            if (warpN == win) {
#pragma unroll
                for (int t = 0; t < 2; t++)
#pragma unroll
                    for (int j = 0; j < 7; j++)
#pragma unroll
                        for (int e = 0; e < 4; e++) {
                            int hrow = e >> 1;
                            int co = m0 + t * 16 + (lane >> 2) + hrow * 8;
                            int ql = j * 8 + (lane & 3) * 2 + (e & 1);
                            fs[co * 57 + ql] =
                                fmaf(acc[t][j][e], sc[t][hrow], bc[t][hrow]);
                        }
            }
            __syncthreads();
            for (int i = tid; i < 128 * 56; i += 256) {
                int co = i / 56, ql = i - co * 56;
                int c = ql >> 3, r = ql & 7;
                long g = ((long)(n * 128 + co) * 56 + h0 + r) * 56 + c0 + win * 7 + c;
                float v = fs[co * 57 + ql] + resid[g];
                outp[g] = fmaxf(v, 0.0f);
            }
        }
    }
}

extern "C" void kernel_launch(void* const* d_in, const int* in_sizes, int n_in,
                              void* d_out, int out_size)
{
    const float* x      = (const float*)d_in[0];
    const float* w1     = (const float*)d_in[1];
    const float* w2     = (const float*)d_in[2];
    const float* gamma1 = (const float*)d_in[3];
    const float* beta1  = (const float*)d_in[4];
    const float* mean1  = (const float*)d_in[5];
    const float* var1   = (const float*)d_in[6];
    const float* gamma2 = (const float*)d_in[7];
    const float* beta2  = (const float*)d_in[8];
    const float* mean2  = (const float*)d_in[9];
    const float* var2   = (const float*)d_in[10];
    float* out = (float*)d_out;

    cudaFuncSetAttribute(conv_mma<0>, cudaFuncAttributeMaxDynamicSharedMemorySize, SMEM_BYTES);
    cudaFuncSetAttribute(conv_mma<1>, cudaFuncAttributeMaxDynamicSharedMemorySize, SMEM_BYTES);

    prep_x<<<dim3(HHH, NB), 256>>>(x);
    prep_w<<<(2 * WF_U32 + 255) / 256, 256>>>(w1, w2);

    dim3 grid(4, 7, NB);
    conv_mma<0><<<grid, 256, SMEM_BYTES>>>(gamma1, beta1, mean1, var1, nullptr, nullptr);
    conv_mma<1><<<grid, 256, SMEM_BYTES>>>(gamma2, beta2, mean2, var2, x, out);
}

// round 8
// speedup vs baseline: 9.6152x; 1.0603x over previous
#include <cuda_runtime.h>
#include <cuda_fp16.h>
#include <cstdint>
#include <math.h>

#define NB   64
#define HHH  56
#define WWW  56
#define EPS  1e-5f

// ---------------- global scratch (no cudaMalloc allowed) ----------------
#define NHWC_ELEMS (NB * HHH * WWW * 128)
__device__ __align__(16) __half g_xf[NHWC_ELEMS];
__device__ __align__(16) __half g_mf[NHWC_ELEMS];

// W fragment-major: [conv][ ((tap*8 + mtile)*8 + kg)*128 + lane*4 + r ], fp16 pairs.
#define WF_U32 (9 * 8 * 8 * 128)
__device__ __align__(16) uint32_t g_wf[2][WF_U32];

// ---------------- smem ----------------
// X slot: 160 rows (16 cols x 10 h) x 80B (32 ci fp16 = 64B + 16 pad). 2 slots.
#define X_SLOT     12800
#define SMEM_BYTES 29184   // max(2*X_SLOT=25600, MODE0 eb=28672, MODE1 fs=29184)

__device__ __forceinline__ uint32_t smem_u32(const void* p) {
    uint32_t a;
    asm("{ .reg .u64 t; cvta.to.shared.u64 t, %1; cvt.u32.u64 %0, t; }" : "=r"(a) : "l"(p));
    return a;
}
__device__ __forceinline__ void cp16(uint32_t dst, const void* src, uint32_t sz) {
    asm volatile("cp.async.cg.shared.global [%0], [%1], 16, %2;"
                 :: "r"(dst), "l"(src), "r"(sz));
}
#define CP_COMMIT() asm volatile("cp.async.commit_group;" ::: "memory")
#define CP_WAIT0()  asm volatile("cp.async.wait_group 0;" ::: "memory")

#define LDSM_X4(r, addr)                                                       \
    asm volatile("ldmatrix.sync.aligned.m8n8.x4.shared.b16 {%0,%1,%2,%3}, [%4];" \
        : "=r"((r)[0]), "=r"((r)[1]), "=r"((r)[2]), "=r"((r)[3]) : "r"(addr))

__device__ __forceinline__ void mma16816(float* d, const uint32_t* a, const uint32_t* b) {
    asm volatile(
        "mma.sync.aligned.m16n8k16.row.col.f32.f16.f16.f32 "
        "{%0,%1,%2,%3}, {%4,%5,%6,%7}, {%8,%9}, {%0,%1,%2,%3};"
        : "+f"(d[0]), "+f"(d[1]), "+f"(d[2]), "+f"(d[3])
        : "r"(a[0]), "r"(a[1]), "r"(a[2]), "r"(a[3]), "r"(b[0]), "r"(b[1]));
}

// ---- prep: NCHW fp32 x -> NHWC fp16 ----
__global__ void prep_x(const float* __restrict__ x) {
    __shared__ float s[128][57];
    const int n = blockIdx.y, h = blockIdx.x;
    for (int i = threadIdx.x; i < 128 * 56; i += blockDim.x) {
        int ci = i / 56, w = i - ci * 56;
        s[ci][w] = x[((long)(n * 128 + ci) * 56 + h) * 56 + w];
    }
    __syncthreads();
    for (int i = threadIdx.x; i < 128 * 56; i += blockDim.x) {
        int w = i >> 7, ci = i & 127;
        long idx = ((long)(n * 56 + h) * 56 + w) * 128 + ci;
        g_xf[idx] = __float2half(s[ci][w]);
    }
}

// ---- prep: OIHW fp32 w -> fragment-major fp16 ----
__global__ void prep_w(const float* __restrict__ w1, const float* __restrict__ w2) {
    int i = blockIdx.x * blockDim.x + threadIdx.x;
    if (i >= 2 * WF_U32) return;
    int conv = i / WF_U32;
    int r2   = i - conv * WF_U32;
    int tap  = r2 >> 13;
    int mt   = (r2 >> 10) & 7;
    int kg   = (r2 >> 7) & 7;
    int lane = (r2 >> 2) & 31;
    int r    = r2 & 3;
    int co = mt * 16 + (lane >> 2) + (r & 1) * 8;
    int ci = kg * 16 + (lane & 3) * 2 + (r >> 1) * 8;
    int kh = tap / 3, kw = tap - kh * 3;
    const float* w = conv ? w2 : w1;
    __half h0 = __float2half(w[((co * 128 + ci) * 3 + kh) * 3 + kw]);
    __half h1 = __float2half(w[((co * 128 + ci + 1) * 3 + kh) * 3 + kw]);
    g_wf[conv][r2] = (uint32_t)__half_as_ushort(h0) |
                     ((uint32_t)__half_as_ushort(h1) << 16);
}

// MODE 0: src g_xf, w1, BN1, relu -> g_mf (NHWC fp16)
// MODE 1: src g_mf, w2, BN2, +x(NCHW), relu -> out (NCHW fp32)
template <int MODE>
__global__ void __launch_bounds__(256, 2)
conv_mma(const float* __restrict__ gamma, const float* __restrict__ beta,
         const float* __restrict__ mean,  const float* __restrict__ var,
         const float* __restrict__ resid, float* __restrict__ outp)
{
    extern __shared__ char smem[];
    const uint32_t sb = smem_u32(smem);
    const int tid  = threadIdx.x;
    const int lane = tid & 31;
    const int wid  = tid >> 5;
    const int warpM = wid & 3;
    const int warpN = wid >> 2;
    const int n  = blockIdx.z;
    const int h0 = blockIdx.y * 8;
    const int c0 = blockIdx.x * 14;

    const __half* src = (MODE == 0) ? g_xf : g_mf;
    const uint32_t* wf = &g_wf[MODE][(size_t)(warpM * 2) * 1024 + lane * 4];

    auto stage_x = [&](int chunk) {
        const int ci0 = chunk * 32;
        const uint32_t xb = sb + (uint32_t)(chunk & 1) * X_SLOT;
        for (int i = tid; i < 640; i += 256) {
            int row = i >> 2, seg = i & 3;
            int cx = row / 10, rh = row - cx * 10;
            int h = h0 + rh - 1, w = c0 + cx - 1;
            bool ok = ((unsigned)h < 56u) && ((unsigned)w < 56u);
            long gi = (((long)(n * 56 + (ok ? h : 0)) * 56 + (ok ? w : 0)) * 128
                       + ci0 + seg * 8);
            cp16(xb + row * 80 + seg * 16, src + gi, ok ? 16u : 0u);
        }
    };

    float acc[2][7][4];
#pragma unroll
    for (int t = 0; t < 2; t++)
#pragma unroll
        for (int j = 0; j < 7; j++)
#pragma unroll
            for (int e = 0; e < 4; e++)
                acc[t][j][e] = 0.0f;

    const int m0 = warpM * 32;
    const uint32_t b_off4 = (uint32_t)(lane & 7) * 80 + ((lane >> 3) & 3) * 16;

    stage_x(0); CP_COMMIT();

#pragma unroll 1
    for (int chunk = 0; chunk < 4; chunk++) {
        CP_WAIT0();
        __syncthreads();
        if (chunk < 3) { stage_x(chunk + 1); CP_COMMIT(); }

        const uint32_t xb = sb + (uint32_t)(chunk & 1) * X_SLOT;
#pragma unroll 1
        for (int kh = 0; kh < 3; kh++) {
            // 9 shared B fragments cover all 3 kw taps of this kh
            uint32_t bq[9][4];
#pragma unroll
            for (int m = 0; m < 9; m++)
                LDSM_X4(bq[m],
                    xb + (uint32_t)((warpN * 7 + m) * 10 + kh) * 80 + b_off4);

#pragma unroll
            for (int kw = 0; kw < 3; kw++) {
                const int tap = kh * 3 + kw;
                uint32_t a[2][2][4];   // [k16][mtile]
#pragma unroll
                for (int k16 = 0; k16 < 2; k16++)
#pragma unroll
                    for (int mt = 0; mt < 2; mt++)
                        *reinterpret_cast<uint4*>(a[k16][mt]) =
                            *reinterpret_cast<const uint4*>(
                                wf + tap * 8192 + mt * 1024 + (chunk * 2 + k16) * 128);
#pragma unroll
                for (int j = 0; j < 7; j++) {
                    mma16816(acc[0][j], a[0][0], bq[kw + j]);
                    mma16816(acc[1][j], a[0][1], bq[kw + j]);
                    mma16816(acc[0][j], a[1][0], bq[kw + j] + 2);
                    mma16816(acc[1][j], a[1][1], bq[kw + j] + 2);
                }
            }
        }
    }

    // ---------------- epilogue ----------------
    float sc[2][2], bc[2][2];
#pragma unroll
    for (int t = 0; t < 2; t++)
#pragma unroll
        for (int hrow = 0; hrow < 2; hrow++) {
            int co = m0 + t * 16 + (lane >> 2) + hrow * 8;
            float s = gamma[co] * rsqrtf(var[co] + EPS);
            sc[t][hrow] = s;
            bc[t][hrow] = beta[co] - mean[co] * s;
        }

    if (MODE == 0) {
        __half* eb = reinterpret_cast<__half*>(smem);   // [112 q][128 co]
        __syncthreads();
#pragma unroll
        for (int t = 0; t < 2; t++)
#pragma unroll
            for (int j = 0; j < 7; j++)
#pragma unroll
                for (int e = 0; e < 4; e++) {
                    int hrow = e >> 1;
                    int co = m0 + t * 16 + (lane >> 2) + hrow * 8;
                    int q  = warpN * 56 + j * 8 + (lane & 3) * 2 + (e & 1);
                    float v = fmaxf(fmaf(acc[t][j][e], sc[t][hrow], bc[t][hrow]), 0.0f);
                    eb[q * 128 + co] = __float2half(v);
                }
        __syncthreads();
        for (int i = tid; i < 1792; i += 256) {
            int q = i >> 4, seg = i & 15;
            uint4 v = reinterpret_cast<const uint4*>(eb)[i];
            *reinterpret_cast<uint4*>(g_mf +
                ((long)((n * 56 + h0 + (q & 7)) * 56 + c0 + (q >> 3))) * 128 + seg * 8) = v;
        }
    } else {
        float* fs = reinterpret_cast<float*>(smem);   // [128 co][57]
        for (int win = 0; win < 2; win++) {
            __syncthreads();
            if (warpN == win) {
#pragma unroll
                for (int t = 0; t < 2; t++)
#pragma unroll
                    for (int j = 0; j < 7; j++)
#pragma unroll
                        for (int e = 0; e < 4; e++) {
                            int hrow = e >> 1;
                            int co = m0 + t * 16 + (lane >> 2) + hrow * 8;
                            int ql = j * 8 + (lane & 3) * 2 + (e & 1);
                            fs[co * 57 + ql] =
                                fmaf(acc[t][j][e], sc[t][hrow], bc[t][hrow]);
                        }
            }
            __syncthreads();
            for (int i = tid; i < 128 * 56; i += 256) {
                int co = i / 56, ql = i - co * 56;
                int c = ql >> 3, r = ql & 7;
                long g = ((long)(n * 128 + co) * 56 + h0 + r) * 56 + c0 + win * 7 + c;
                float v = fs[co * 57 + ql] + resid[g];
                outp[g] = fmaxf(v, 0.0f);
            }
        }
    }
}

extern "C" void kernel_launch(void* const* d_in, const int* in_sizes, int n_in,
                              void* d_out, int out_size)
{
    const float* x      = (const float*)d_in[0];
    const float* w1     = (const float*)d_in[1];
    const float* w2     = (const float*)d_in[2];
    const float* gamma1 = (const float*)d_in[3];
    const float* beta1  = (const float*)d_in[4];
    const float* mean1  = (const float*)d_in[5];
    const float* var1   = (const float*)d_in[6];
    const float* gamma2 = (const float*)d_in[7];
    const float* beta2  = (const float*)d_in[8];
    const float* mean2  = (const float*)d_in[9];
    const float* var2   = (const float*)d_in[10];
    float* out = (float*)d_out;

    cudaFuncSetAttribute(conv_mma<0>, cudaFuncAttributeMaxDynamicSharedMemorySize, SMEM_BYTES);
    cudaFuncSetAttribute(conv_mma<1>, cudaFuncAttributeMaxDynamicSharedMemorySize, SMEM_BYTES);

    prep_x<<<dim3(HHH, NB), 256>>>(x);
    prep_w<<<(2 * WF_U32 + 255) / 256, 256>>>(w1, w2);

    dim3 grid(4, 7, NB);
    conv_mma<0><<<grid, 256, SMEM_BYTES>>>(gamma1, beta1, mean1, var1, nullptr, nullptr);
    conv_mma<1><<<grid, 256, SMEM_BYTES>>>(gamma2, beta2, mean2, var2, x, out);
}